// round 14
// baseline (speedup 1.0000x reference)
#include <cuda_runtime.h>
#include <cuda_fp16.h>
#include <cuda_bf16.h>
#include <cstdint>

#define B_SZ 512
#define L_SZ 128
#define F3   900
#define DM   512
#define DLLM 4096
#define NE   8
#define EPS_RENORM 1e-9f

#define BK      64
#define KTILES  15          // 14 full + 1 partial (only ks=0 live: 896+16 >= 900)
#define KPAD    960
#define NCHUNK  8
#define NCROWS  64          // DM / NCHUNK
#define THREADS 256
#define NTILES_TOT 4096     // NCHUNK * B_SZ

// smem stage layout (Swizzle<3,4,3> on 128B rows)
#define A_OFF  0
#define B_OFF  16384
#define STG    32768        // A 16KB + B (64E+64G rows x 128B) 16KB
#define NBUF   3
#define SMEM_TOT (NBUF * STG)   // 98304 -> 2 CTAs/SM

// fused-prep block ranges
#define GATE_NB 512
#define A_NB    30720        // 512*128*120 / 256
#define WE_NB   1920         // 8*8*120*64 / 256
#define WG_NB   240          // 8*120*64 / 256

// ---------------- device scratch ----------------
__device__ int   g_eidx[B_SZ];
__device__ float g_scale[B_SZ];
__device__ __align__(16) float g_beff[B_SZ * DM];
__device__ __align__(16) float g_bgsum[DM];
// fp16 weights (single image): [e][nc][n 64][k 960]
__device__ __align__(16) __half g_BE[(size_t)NE * NCHUNK * NCROWS * KPAD];
__device__ __align__(16) __half g_BG[(size_t)NCHUNK * NCROWS * KPAD];
// fp16 activations (single image): [b][m 128][k 960]
__device__ __align__(16) __half g_AH[(size_t)B_SZ * L_SZ * KPAD];

// ---------------- helpers ----------------
__device__ __forceinline__ uint32_t smem_u32(const void* p) {
    uint32_t a;
    asm("{ .reg .u64 t; cvta.to.shared.u64 t, %1; cvt.u32.u64 %0, t; }" : "=r"(a) : "l"(p));
    return a;
}
__device__ __forceinline__ uint32_t sw(uint32_t off) {    // Swizzle<3,4,3> (128B rows)
    return off ^ (((off >> 7) & 7u) << 4);
}
__device__ __forceinline__ void ldsm4(uint32_t* r, uint32_t addr) {
    asm volatile("ldmatrix.sync.aligned.m8n8.x4.shared.b16 {%0,%1,%2,%3}, [%4];"
                 : "=r"(r[0]), "=r"(r[1]), "=r"(r[2]), "=r"(r[3]) : "r"(addr));
}
__device__ __forceinline__ void hmma(float* c, const uint32_t* a, uint32_t b0, uint32_t b1) {
    asm volatile(
        "mma.sync.aligned.m16n8k16.row.col.f32.f16.f16.f32 "
        "{%0,%1,%2,%3}, {%4,%5,%6,%7}, {%8,%9}, {%0,%1,%2,%3};"
        : "+f"(c[0]), "+f"(c[1]), "+f"(c[2]), "+f"(c[3])
        : "r"(a[0]), "r"(a[1]), "r"(a[2]), "r"(a[3]), "r"(b0), "r"(b1));
}
__device__ __forceinline__ void cpasync16(uint32_t dst, const void* src) {
    asm volatile("cp.async.cg.shared.global [%0], [%1], 16;" :: "r"(dst), "l"(src));
}
#define CP_COMMIT() asm volatile("cp.async.commit_group;" ::: "memory")
#define CP_WAIT1()  asm volatile("cp.async.wait_group 1;" ::: "memory")

// ============================================================
// Fused prep kernel: block-range partitioned, one launch.
// (unchanged from R13)
// ============================================================
__global__ __launch_bounds__(THREADS) void prep_all(
    const float* __restrict__ x,
    const float* __restrict__ dkp, const float* __restrict__ Wg,
    const float* __restrict__ bg,  const float* __restrict__ bexp,
    const float* __restrict__ We,
    const float* __restrict__ Wgen, const float* __restrict__ bgen)
{
    const int bid = blockIdx.x;
    const int tid = threadIdx.x;

    if (bid < GATE_NB) {
        // ---------------- gate ----------------
        const int b = bid;
        float acc[NE];
#pragma unroll
        for (int e = 0; e < NE; e++) acc[e] = 0.f;
        const float4* dk4 = reinterpret_cast<const float4*>(dkp + (size_t)b * DLLM);
        for (int k4 = tid; k4 < DLLM / 4; k4 += THREADS) {
            float4 xv4 = dk4[k4];
            float xs[4] = {xv4.x, xv4.y, xv4.z, xv4.w};
#pragma unroll
            for (int j = 0; j < 4; j++) {
                const float4* wr = reinterpret_cast<const float4*>(Wg + (size_t)(k4 * 4 + j) * NE);
                float4 w0 = wr[0], w1 = wr[1];
                float xv = xs[j];
                acc[0] += xv * w0.x; acc[1] += xv * w0.y; acc[2] += xv * w0.z; acc[3] += xv * w0.w;
                acc[4] += xv * w1.x; acc[5] += xv * w1.y; acc[6] += xv * w1.z; acc[7] += xv * w1.w;
            }
        }
        __shared__ float red[THREADS][NE];
#pragma unroll
        for (int e = 0; e < NE; e++) red[tid][e] = acc[e];
        __syncthreads();
        for (int s = THREADS / 2; s > 0; s >>= 1) {
            if (tid < s) {
#pragma unroll
                for (int e = 0; e < NE; e++) red[tid][e] += red[tid + s][e];
            }
            __syncthreads();
        }
        __shared__ int se;
        __shared__ float ss;
        if (tid == 0) {
            float logit[NE], p[NE], mx = -1e30f;
#pragma unroll
            for (int e = 0; e < NE; e++) { logit[e] = red[0][e] + bg[e]; mx = fmaxf(mx, logit[e]); }
            float s = 0.f;
#pragma unroll
            for (int e = 0; e < NE; e++) { p[e] = expf(logit[e] - mx); s += p[e]; }
            int best = 0;
#pragma unroll
            for (int e = 1; e < NE; e++) if (p[e] > p[best]) best = e;
            float pb = p[best] / s;
            float scale = pb / (pb + EPS_RENORM);
            se = best; ss = scale;
            g_eidx[b] = best; g_scale[b] = scale;
        }
        __syncthreads();
        int e = se; float sc = ss;
        for (int d = tid; d < DM; d += THREADS)
            g_beff[(size_t)b * DM + d] = sc * bexp[e * DM + d];
        return;
    }

    if (bid < GATE_NB + A_NB) {
        // ---------------- prep_a (vectorized float4 loads) ----------------
        int t = (bid - GATE_NB) * THREADS + tid;
        int q = t % 120;
        int m = (t / 120) % L_SZ;
        int b = t / (120 * L_SZ);
        int k0 = q * 8;
        const float* xr = x + ((size_t)b * L_SZ + m) * F3;
        float4 v0 = make_float4(0.f, 0.f, 0.f, 0.f);
        float4 v1 = make_float4(0.f, 0.f, 0.f, 0.f);
        if (q < 112) {
            v0 = *reinterpret_cast<const float4*>(xr + k0);
            v1 = *reinterpret_cast<const float4*>(xr + k0 + 4);
        } else if (q == 112) {
            v0 = *reinterpret_cast<const float4*>(xr + k0);
        }
        union { __half h[8]; uint4 v; } uh;
        uh.h[0] = __float2half_rn(v0.x); uh.h[1] = __float2half_rn(v0.y);
        uh.h[2] = __float2half_rn(v0.z); uh.h[3] = __float2half_rn(v0.w);
        uh.h[4] = __float2half_rn(v1.x); uh.h[5] = __float2half_rn(v1.y);
        uh.h[6] = __float2half_rn(v1.z); uh.h[7] = __float2half_rn(v1.w);
        size_t o = ((size_t)b * L_SZ + m) * KPAD + k0;
        *reinterpret_cast<uint4*>(&g_AH[o]) = uh.v;
        return;
    }

    if (bid < GATE_NB + A_NB + WE_NB) {
        // ---------------- prep_we ----------------
        int t = (bid - GATE_NB - A_NB) * THREADS + tid;
        int n  = t & 63;
        int r  = t >> 6;
        int kg = r % 120; r /= 120;
        int nc = r & 7;   int e = r >> 3;
        int k0 = kg * 8;
        union { __half h[8]; uint4 v; } uh;
#pragma unroll
        for (int j = 0; j < 8; j++) {
            int k = k0 + j;
            float v = (k < F3) ? We[(size_t)e * F3 * DM + (size_t)k * DM + nc * NCROWS + n] : 0.f;
            uh.h[j] = __float2half_rn(v);
        }
        size_t base = (size_t)(e * NCHUNK + nc) * (NCROWS * KPAD) + (size_t)n * KPAD + k0;
        *reinterpret_cast<uint4*>(&g_BE[base]) = uh.v;
        return;
    }

    {
        // ---------------- prep_wg + bgsum ----------------
        int t = (bid - GATE_NB - A_NB - WE_NB) * THREADS + tid;
        if (t < DM) g_bgsum[t] = bgen[t] + bgen[DM + t];
        int n  = t & 63;
        int r  = t >> 6;
        int kg = r % 120;
        int nc = r / 120;
        int k0 = kg * 8;
        union { __half h[8]; uint4 v; } uh;
#pragma unroll
        for (int j = 0; j < 8; j++) {
            int k = k0 + j;
            float v = 0.f;
            if (k < F3) {
                size_t idx = (size_t)k * DM + nc * NCROWS + n;
                v = Wgen[idx] + Wgen[(size_t)F3 * DM + idx];
            }
            uh.h[j] = __float2half_rn(v);
        }
        size_t base = (size_t)nc * (NCROWS * KPAD) + (size_t)n * KPAD + k0;
        *reinterpret_cast<uint4*>(&g_BG[base]) = uh.v;
    }
}

// ============================================================
// Main GEMM: PERSISTENT CTAs. ncta = 2*SMs (multiple of 8).
// CTA walks tiles g = cta + k*ncta; nc = g&7 is CONSTANT per CTA,
// b = g>>3 strides. The cp.async pipeline flows continuously across
// tile boundaries (no per-tile drain/refill); epilogue overlaps the
// next tile's in-flight loads. Flat stage counter S: buffer = S%3,
// commit every iteration, issue(S+2) while S+2 < S_end.
// KS bodies / fragment maps / epilogue math identical to R13.
// ============================================================
__global__ __launch_bounds__(THREADS, 2) void moe_mma(float* __restrict__ out, int ncta)
{
    extern __shared__ char sm[];
    const int cta = blockIdx.x;
    const int tid = threadIdx.x, lane = tid & 31, warp = tid >> 5;
    const int wm = warp & 3, wn = warp >> 2;
    const int m0 = wm * 32, n0 = wn * 32;
    const uint32_t sbase = smem_u32(sm);

    const int nc = cta & 7;            // constant per CTA (ncta % 8 == 0)
    const __half* bgW = g_BG + (size_t)nc * (NCROWS * KPAD);
    const float*  bgs = g_bgsum + nc * NCROWS;

    const int ntiles = (NTILES_TOT - cta + ncta - 1) / ncta;
    const int S_end  = ntiles * KTILES;

    float accE[2][4][4], accG[2][4][4];
#pragma unroll
    for (int i = 0; i < 2; i++)
#pragma unroll
        for (int j = 0; j < 4; j++)
#pragma unroll
            for (int c = 0; c < 4; c++) { accE[i][j][c] = 0.f; accG[i][j][c] = 0.f; }

    const int arow  = (lane & 7) + 8 * ((lane >> 3) & 1);
    const int acol8 = (lane >> 4);
    const int brow  = (lane & 7) + 8 * (lane >> 4);
    const int bcol8 = (lane >> 3) & 1;

    auto issue = [&](int S) {
        const int t = S / KTILES;
        const int s = S - t * KTILES;
        const int g = cta + t * ncta;
        const int b = g >> 3;
        const __half* aH  = g_AH + (size_t)b * L_SZ * KPAD;
        const __half* beW = g_BE + (size_t)(g_eidx[b] * NCHUNK + nc) * (NCROWS * KPAD);
        const uint32_t sb = sbase + (S % NBUF) * STG;
#pragma unroll
        for (int tt = 0; tt < 4; tt++) {
            int c = tid + tt * 256;
            int m = (c >> 3) & 127, q = c & 7;
            uint32_t off = sw((uint32_t)m * 128 + q * 16);
            const __half* src = aH + (size_t)m * KPAD + s * BK + q * 8;
            cpasync16(sb + A_OFF + off, src);
        }
#pragma unroll
        for (int tt = 0; tt < 4; tt++) {
            int c = tid + tt * 256;
            int r = (c >> 3) & 127, q = c & 7;
            uint32_t off = sw((uint32_t)r * 128 + q * 16);
            const __half* src = (r < NCROWS)
                ? beW + (size_t)r * KPAD + s * BK + q * 8
                : bgW + (size_t)(r - NCROWS) * KPAD + s * BK + q * 8;
            cpasync16(sb + B_OFF + off, src);
        }
    };

#define KS_BODY(bufA, bufB, KS) do { \
        uint32_t ah[2][4], be2[2][4], bg2[2][4]; \
        const uint32_t acoff = (KS) * 32 + acol8 * 16; \
        const uint32_t bcoff = (KS) * 32 + bcol8 * 16; \
        _Pragma("unroll") \
        for (int mt = 0; mt < 2; mt++) { \
            uint32_t ro = (uint32_t)(m0 + mt * 16 + arow) * 128; \
            ldsm4(ah[mt], (bufA) + sw(ro + acoff)); \
        } \
        _Pragma("unroll") \
        for (int pp = 0; pp < 2; pp++) { \
            uint32_t roE = (uint32_t)(n0 + pp * 16 + brow) * 128; \
            uint32_t roG = (uint32_t)(NCROWS + n0 + pp * 16 + brow) * 128; \
            ldsm4(be2[pp], (bufB) + sw(roE + bcoff)); \
            ldsm4(bg2[pp], (bufB) + sw(roG + bcoff)); \
        } \
        _Pragma("unroll") \
        for (int mt = 0; mt < 2; mt++) \
            _Pragma("unroll") \
            for (int nt = 0; nt < 4; nt++) \
                hmma(accE[mt][nt], ah[mt], be2[nt >> 1][(nt & 1) * 2], be2[nt >> 1][(nt & 1) * 2 + 1]); \
        _Pragma("unroll") \
        for (int mt = 0; mt < 2; mt++) \
            _Pragma("unroll") \
            for (int nt = 0; nt < 4; nt++) \
                hmma(accG[mt][nt], ah[mt], bg2[nt >> 1][(nt & 1) * 2], bg2[nt >> 1][(nt & 1) * 2 + 1]); \
    } while (0)

    issue(0); CP_COMMIT();
    issue(1); CP_COMMIT();

    for (int S = 0; S < S_end; S++) {
        CP_WAIT1();
        __syncthreads();

        const int t = S / KTILES;
        const int s = S - t * KTILES;
        const uint32_t bufA = sbase + (S % NBUF) * STG;
        const uint32_t bufB = bufA + B_OFF;

        KS_BODY(bufA, bufB, 0);
        if (S + 2 < S_end) issue(S + 2);
        CP_COMMIT();

        if (s < KTILES - 1) {
            KS_BODY(bufA, bufB, 1);
            KS_BODY(bufA, bufB, 2);
            KS_BODY(bufA, bufB, 3);
        } else {
            // ---- tile epilogue (k 896..912 of KS0 covered F3=900) ----
            const int g = cta + t * ncta;
            const int b = g >> 3;
            const float sc = g_scale[b];
            const float* beff = g_beff + (size_t)b * DM + nc * NCROWS;
#pragma unroll
            for (int mt = 0; mt < 2; mt++) {
                int mb = m0 + mt * 16 + (lane >> 2);
#pragma unroll
                for (int nt = 0; nt < 4; nt++) {
                    int nlb = n0 + nt * 8 + 2 * (lane & 3);
                    float be_0 = __ldg(&beff[nlb]),  be_1 = __ldg(&beff[nlb + 1]);
                    float bg_0 = __ldg(&bgs[nlb]),   bg_1 = __ldg(&bgs[nlb + 1]);
#pragma unroll
                    for (int h = 0; h < 2; h++) {
                        int mm = mb + 8 * h;
                        float ev0 = sc * accE[mt][nt][h * 2 + 0] + be_0;
                        float ev1 = sc * accE[mt][nt][h * 2 + 1] + be_1;
                        float2 o;
                        o.x = __bfloat162float(__float2bfloat16(ev0)) + accG[mt][nt][h * 2 + 0] + bg_0;
                        o.y = __bfloat162float(__float2bfloat16(ev1)) + accG[mt][nt][h * 2 + 1] + bg_1;
                        *reinterpret_cast<float2*>(
                            out + ((size_t)b * L_SZ + mm) * DM + nc * NCROWS + nlb) = o;
                    }
                }
            }
#pragma unroll
            for (int i = 0; i < 2; i++)
#pragma unroll
                for (int j = 0; j < 4; j++)
#pragma unroll
                    for (int c = 0; c < 4; c++) { accE[i][j][c] = 0.f; accG[i][j][c] = 0.f; }
        }
    }
#undef KS_BODY
}

// ============================================================
extern "C" void kernel_launch(void* const* d_in, const int* in_sizes, int n_in,
                              void* d_out, int out_size)
{
    const float* x     = (const float*)d_in[0];
    const float* dkp   = (const float*)d_in[1];
    const float* Wexp  = (const float*)d_in[2];
    const float* bexp  = (const float*)d_in[3];
    const float* Wgen  = (const float*)d_in[4];
    const float* bgen  = (const float*)d_in[5];
    const float* Wgate = (const float*)d_in[6];
    const float* bgate = (const float*)d_in[7];
    float* out = (float*)d_out;

    cudaFuncSetAttribute(moe_mma, cudaFuncAttributeMaxDynamicSharedMemorySize, SMEM_TOT);

    const int total_blocks = GATE_NB + A_NB + WE_NB + WG_NB;
    prep_all<<<total_blocks, THREADS>>>(x, dkp, Wgate, bgate, bexp, Wexp, Wgen, bgen);

    int nsm = 0;
    cudaDeviceGetAttribute(&nsm, cudaDevAttrMultiProcessorCount, 0);
    int ncta = (2 * nsm) & ~7;          // 2 CTAs/SM, multiple of 8 (nc constancy)
    if (ncta < 8) ncta = 8;
    if (ncta > NTILES_TOT) ncta = NTILES_TOT;

    moe_mma<<<ncta, THREADS, SMEM_TOT>>>(out, ncta);
}

// round 15
// speedup vs baseline: 1.0561x; 1.0561x over previous
#include <cuda_runtime.h>
#include <cuda_fp16.h>
#include <cuda_bf16.h>
#include <cstdint>

#define B_SZ 512
#define L_SZ 128
#define F3   900
#define DM   512
#define DLLM 4096
#define NE   8
#define EPS_RENORM 1e-9f

#define BK      64
#define KTILES  15          // 14 full + 1 partial (only ks=0 live: 896+16 >= 900)
#define KPAD    960
#define NCHUNK  8
#define NCROWS  64          // DM / NCHUNK
#define THREADS 256

// smem stage layout (Swizzle<3,4,3> on 128B rows)
#define A_OFF  0
#define B_OFF  16384
#define STG    32768        // A 16KB + B (64E+64G rows x 128B) 16KB
#define NBUF   3
#define SMEM_TOT (NBUF * STG)   // 98304 -> 2 CTAs/SM

// fused-prep block ranges
#define GATE_NB 512
#define A_NB    30720        // 512*128*120 / 256
#define WE_NB   1920         // 8*8*120*64 / 256
#define WG_NB   240          // 8*120*64 / 256

// ---------------- device scratch ----------------
__device__ int   g_eidx[B_SZ];
__device__ float g_scale[B_SZ];
__device__ __align__(16) float g_beff[B_SZ * DM];
__device__ __align__(16) float g_bgsum[DM];
// fp16 weights (single image): [e][nc][n 64][k 960]
__device__ __align__(16) __half g_BE[(size_t)NE * NCHUNK * NCROWS * KPAD];
__device__ __align__(16) __half g_BG[(size_t)NCHUNK * NCROWS * KPAD];
// fp16 activations (single image): [b][m 128][k 960]
__device__ __align__(16) __half g_AH[(size_t)B_SZ * L_SZ * KPAD];

// ---------------- helpers ----------------
__device__ __forceinline__ uint32_t smem_u32(const void* p) {
    uint32_t a;
    asm("{ .reg .u64 t; cvta.to.shared.u64 t, %1; cvt.u32.u64 %0, t; }" : "=r"(a) : "l"(p));
    return a;
}
__device__ __forceinline__ uint32_t sw(uint32_t off) {    // Swizzle<3,4,3> (128B rows)
    return off ^ (((off >> 7) & 7u) << 4);
}
__device__ __forceinline__ void ldsm4(uint32_t* r, uint32_t addr) {
    asm volatile("ldmatrix.sync.aligned.m8n8.x4.shared.b16 {%0,%1,%2,%3}, [%4];"
                 : "=r"(r[0]), "=r"(r[1]), "=r"(r[2]), "=r"(r[3]) : "r"(addr));
}
__device__ __forceinline__ void hmma(float* c, const uint32_t* a, uint32_t b0, uint32_t b1) {
    asm volatile(
        "mma.sync.aligned.m16n8k16.row.col.f32.f16.f16.f32 "
        "{%0,%1,%2,%3}, {%4,%5,%6,%7}, {%8,%9}, {%0,%1,%2,%3};"
        : "+f"(c[0]), "+f"(c[1]), "+f"(c[2]), "+f"(c[3])
        : "r"(a[0]), "r"(a[1]), "r"(a[2]), "r"(a[3]), "r"(b0), "r"(b1));
}
__device__ __forceinline__ void cpasync16(uint32_t dst, const void* src) {
    asm volatile("cp.async.cg.shared.global [%0], [%1], 16;" :: "r"(dst), "l"(src));
}
#define CP_COMMIT() asm volatile("cp.async.commit_group;" ::: "memory")
#define CP_WAIT1()  asm volatile("cp.async.wait_group 1;" ::: "memory")

// ============================================================
// Fused prep kernel: block-range partitioned, one launch.
// (unchanged from R13)
// ============================================================
__global__ __launch_bounds__(THREADS) void prep_all(
    const float* __restrict__ x,
    const float* __restrict__ dkp, const float* __restrict__ Wg,
    const float* __restrict__ bg,  const float* __restrict__ bexp,
    const float* __restrict__ We,
    const float* __restrict__ Wgen, const float* __restrict__ bgen)
{
    const int bid = blockIdx.x;
    const int tid = threadIdx.x;

    if (bid < GATE_NB) {
        // ---------------- gate ----------------
        const int b = bid;
        float acc[NE];
#pragma unroll
        for (int e = 0; e < NE; e++) acc[e] = 0.f;
        const float4* dk4 = reinterpret_cast<const float4*>(dkp + (size_t)b * DLLM);
        for (int k4 = tid; k4 < DLLM / 4; k4 += THREADS) {
            float4 xv4 = dk4[k4];
            float xs[4] = {xv4.x, xv4.y, xv4.z, xv4.w};
#pragma unroll
            for (int j = 0; j < 4; j++) {
                const float4* wr = reinterpret_cast<const float4*>(Wg + (size_t)(k4 * 4 + j) * NE);
                float4 w0 = wr[0], w1 = wr[1];
                float xv = xs[j];
                acc[0] += xv * w0.x; acc[1] += xv * w0.y; acc[2] += xv * w0.z; acc[3] += xv * w0.w;
                acc[4] += xv * w1.x; acc[5] += xv * w1.y; acc[6] += xv * w1.z; acc[7] += xv * w1.w;
            }
        }
        __shared__ float red[THREADS][NE];
#pragma unroll
        for (int e = 0; e < NE; e++) red[tid][e] = acc[e];
        __syncthreads();
        for (int s = THREADS / 2; s > 0; s >>= 1) {
            if (tid < s) {
#pragma unroll
                for (int e = 0; e < NE; e++) red[tid][e] += red[tid + s][e];
            }
            __syncthreads();
        }
        __shared__ int se;
        __shared__ float ss;
        if (tid == 0) {
            float logit[NE], p[NE], mx = -1e30f;
#pragma unroll
            for (int e = 0; e < NE; e++) { logit[e] = red[0][e] + bg[e]; mx = fmaxf(mx, logit[e]); }
            float s = 0.f;
#pragma unroll
            for (int e = 0; e < NE; e++) { p[e] = expf(logit[e] - mx); s += p[e]; }
            int best = 0;
#pragma unroll
            for (int e = 1; e < NE; e++) if (p[e] > p[best]) best = e;
            float pb = p[best] / s;
            float scale = pb / (pb + EPS_RENORM);
            se = best; ss = scale;
            g_eidx[b] = best; g_scale[b] = scale;
        }
        __syncthreads();
        int e = se; float sc = ss;
        for (int d = tid; d < DM; d += THREADS)
            g_beff[(size_t)b * DM + d] = sc * bexp[e * DM + d];
        return;
    }

    if (bid < GATE_NB + A_NB) {
        // ---------------- prep_a (vectorized float4 loads) ----------------
        int t = (bid - GATE_NB) * THREADS + tid;
        int q = t % 120;
        int m = (t / 120) % L_SZ;
        int b = t / (120 * L_SZ);
        int k0 = q * 8;
        const float* xr = x + ((size_t)b * L_SZ + m) * F3;
        float4 v0 = make_float4(0.f, 0.f, 0.f, 0.f);
        float4 v1 = make_float4(0.f, 0.f, 0.f, 0.f);
        if (q < 112) {
            v0 = *reinterpret_cast<const float4*>(xr + k0);
            v1 = *reinterpret_cast<const float4*>(xr + k0 + 4);
        } else if (q == 112) {
            v0 = *reinterpret_cast<const float4*>(xr + k0);
        }
        union { __half h[8]; uint4 v; } uh;
        uh.h[0] = __float2half_rn(v0.x); uh.h[1] = __float2half_rn(v0.y);
        uh.h[2] = __float2half_rn(v0.z); uh.h[3] = __float2half_rn(v0.w);
        uh.h[4] = __float2half_rn(v1.x); uh.h[5] = __float2half_rn(v1.y);
        uh.h[6] = __float2half_rn(v1.z); uh.h[7] = __float2half_rn(v1.w);
        size_t o = ((size_t)b * L_SZ + m) * KPAD + k0;
        *reinterpret_cast<uint4*>(&g_AH[o]) = uh.v;
        return;
    }

    if (bid < GATE_NB + A_NB + WE_NB) {
        // ---------------- prep_we ----------------
        int t = (bid - GATE_NB - A_NB) * THREADS + tid;
        int n  = t & 63;
        int r  = t >> 6;
        int kg = r % 120; r /= 120;
        int nc = r & 7;   int e = r >> 3;
        int k0 = kg * 8;
        union { __half h[8]; uint4 v; } uh;
#pragma unroll
        for (int j = 0; j < 8; j++) {
            int k = k0 + j;
            float v = (k < F3) ? We[(size_t)e * F3 * DM + (size_t)k * DM + nc * NCROWS + n] : 0.f;
            uh.h[j] = __float2half_rn(v);
        }
        size_t base = (size_t)(e * NCHUNK + nc) * (NCROWS * KPAD) + (size_t)n * KPAD + k0;
        *reinterpret_cast<uint4*>(&g_BE[base]) = uh.v;
        return;
    }

    {
        // ---------------- prep_wg + bgsum ----------------
        int t = (bid - GATE_NB - A_NB - WE_NB) * THREADS + tid;
        if (t < DM) g_bgsum[t] = bgen[t] + bgen[DM + t];
        int n  = t & 63;
        int r  = t >> 6;
        int kg = r % 120;
        int nc = r / 120;
        int k0 = kg * 8;
        union { __half h[8]; uint4 v; } uh;
#pragma unroll
        for (int j = 0; j < 8; j++) {
            int k = k0 + j;
            float v = 0.f;
            if (k < F3) {
                size_t idx = (size_t)k * DM + nc * NCROWS + n;
                v = Wgen[idx] + Wgen[(size_t)F3 * DM + idx];
            }
            uh.h[j] = __float2half_rn(v);
        }
        size_t base = (size_t)nc * (NCROWS * KPAD) + (size_t)n * KPAD + k0;
        *reinterpret_cast<uint4*>(&g_BG[base]) = uh.v;
    }
}

// ============================================================
// Main GEMM (R13 architecture): fp16 mma.sync, expert 1-term,
// gen 1-term (shared A). CTA = (nc, b): out tile 128(L) x 64(d).
// BK=64, 15 stages (stage 14 partial), 3-buffer depth-2 pipeline,
// 2 CTAs/SM. New vs R13: cp.async dst/src offsets hoisted out of
// the stage loop (per-stage work = one add per transfer), and the
// last stage issues only the q<2 quads actually read by KS0.
// ============================================================
__global__ __launch_bounds__(THREADS, 2) void moe_mma(float* __restrict__ out)
{
    extern __shared__ char sm[];
    const int b = blockIdx.y, nc = blockIdx.x;
    const int tid = threadIdx.x, lane = tid & 31, warp = tid >> 5;
    const int wm = warp & 3, wn = warp >> 2;
    const int m0 = wm * 32, n0 = wn * 32;
    const uint32_t sbase = smem_u32(sm);

    const int   e  = g_eidx[b];
    const float sc = g_scale[b];

    const __half* aH = g_AH + (size_t)b * L_SZ * KPAD;
    const __half* beW = g_BE + (size_t)(e * NCHUNK + nc) * (NCROWS * KPAD);
    const __half* bgW = g_BG + (size_t)nc * (NCROWS * KPAD);

    float accE[2][4][4], accG[2][4][4];
#pragma unroll
    for (int i = 0; i < 2; i++)
#pragma unroll
        for (int j = 0; j < 4; j++)
#pragma unroll
            for (int c = 0; c < 4; c++) { accE[i][j][c] = 0.f; accG[i][j][c] = 0.f; }

    const int arow  = (lane & 7) + 8 * ((lane >> 3) & 1);
    const int acol8 = (lane >> 4);
    const int brow  = (lane & 7) + 8 * (lane >> 4);
    const int bcol8 = (lane >> 3) & 1;

    // ---- hoisted cp.async transfer descriptors (loop-invariant) ----
    // q = (tid + t*256) & 7 == tid & 7 for all t (256 % 8 == 0)
    const int q = tid & 7;
    uint32_t dA[4], oA[4];          // smem dst offset / gmem elem offset (A)
    uint32_t dB[4];                 // smem dst offset (B)
    const __half* pB[4];            // gmem base ptr (B, row-resolved)
#pragma unroll
    for (int t = 0; t < 4; t++) {
        int c = tid + t * 256;
        int m = (c >> 3) & 127;
        dA[t] = A_OFF + sw((uint32_t)m * 128 + q * 16);
        oA[t] = (uint32_t)m * KPAD + q * 8;
        int r = (c >> 3) & 127;
        dB[t] = B_OFF + sw((uint32_t)r * 128 + q * 16);
        pB[t] = ((r < NCROWS) ? beW + (size_t)r * KPAD
                              : bgW + (size_t)(r - NCROWS) * KPAD) + q * 8;
    }

    auto issue = [&](int s, int stg) {
        const uint32_t sb = sbase + stg * STG;
        const uint32_t kof = (uint32_t)s * BK;
#pragma unroll
        for (int t = 0; t < 4; t++) cpasync16(sb + dA[t], aH + oA[t] + kof);
#pragma unroll
        for (int t = 0; t < 4; t++) cpasync16(sb + dB[t], pB[t] + kof);
    };

#define KS_BODY(bufA, bufB, KS) do { \
        uint32_t ah[2][4], be2[2][4], bg2[2][4]; \
        const uint32_t acoff = (KS) * 32 + acol8 * 16; \
        const uint32_t bcoff = (KS) * 32 + bcol8 * 16; \
        _Pragma("unroll") \
        for (int mt = 0; mt < 2; mt++) { \
            uint32_t ro = (uint32_t)(m0 + mt * 16 + arow) * 128; \
            ldsm4(ah[mt], (bufA) + sw(ro + acoff)); \
        } \
        _Pragma("unroll") \
        for (int pp = 0; pp < 2; pp++) { \
            uint32_t roE = (uint32_t)(n0 + pp * 16 + brow) * 128; \
            uint32_t roG = (uint32_t)(NCROWS + n0 + pp * 16 + brow) * 128; \
            ldsm4(be2[pp], (bufB) + sw(roE + bcoff)); \
            ldsm4(bg2[pp], (bufB) + sw(roG + bcoff)); \
        } \
        _Pragma("unroll") \
        for (int mt = 0; mt < 2; mt++) \
            _Pragma("unroll") \
            for (int nt = 0; nt < 4; nt++) \
                hmma(accE[mt][nt], ah[mt], be2[nt >> 1][(nt & 1) * 2], be2[nt >> 1][(nt & 1) * 2 + 1]); \
        _Pragma("unroll") \
        for (int mt = 0; mt < 2; mt++) \
            _Pragma("unroll") \
            for (int nt = 0; nt < 4; nt++) \
                hmma(accG[mt][nt], ah[mt], bg2[nt >> 1][(nt & 1) * 2], bg2[nt >> 1][(nt & 1) * 2 + 1]); \
    } while (0)

    issue(0, 0); CP_COMMIT();
    issue(1, 1); CP_COMMIT();

    for (int s = 0; s < KTILES; s++) {
        const int p = s % NBUF;
        CP_WAIT1();
        __syncthreads();

        const uint32_t bufA = sbase + p * STG;
        const uint32_t bufB = bufA + B_OFF;

        if (s < KTILES - 1) {
            KS_BODY(bufA, bufB, 0);
            if (s + 2 < KTILES) {
                if (s + 2 == KTILES - 1) {
                    // last stage: KS0 reads only bytes [0,32) per row -> quads q<2
                    if (q < 2) issue(s + 2, (s + 2) % NBUF);
                } else {
                    issue(s + 2, (s + 2) % NBUF);
                }
            }
            CP_COMMIT();
            KS_BODY(bufA, bufB, 1);
            KS_BODY(bufA, bufB, 2);
            KS_BODY(bufA, bufB, 3);
        } else {
            CP_COMMIT();              // keep group count in lockstep
            KS_BODY(bufA, bufB, 0);   // k 896..912 covers F3=900
        }
    }
#undef KS_BODY

    // ---- register epilogue: all warps store their paired tiles ----
    const float* beff = g_beff + (size_t)b * DM + nc * NCROWS;
    const float* bgs  = g_bgsum + nc * NCROWS;
#pragma unroll
    for (int mt = 0; mt < 2; mt++) {
        int mb = m0 + mt * 16 + (lane >> 2);
#pragma unroll
        for (int nt = 0; nt < 4; nt++) {
            int nlb = n0 + nt * 8 + 2 * (lane & 3);
            float be_0 = __ldg(&beff[nlb]),  be_1 = __ldg(&beff[nlb + 1]);
            float bg_0 = __ldg(&bgs[nlb]),   bg_1 = __ldg(&bgs[nlb + 1]);
#pragma unroll
            for (int h = 0; h < 2; h++) {
                int mm = mb + 8 * h;
                float ev0 = sc * accE[mt][nt][h * 2 + 0] + be_0;
                float ev1 = sc * accE[mt][nt][h * 2 + 1] + be_1;
                float2 o;
                o.x = __bfloat162float(__float2bfloat16(ev0)) + accG[mt][nt][h * 2 + 0] + bg_0;
                o.y = __bfloat162float(__float2bfloat16(ev1)) + accG[mt][nt][h * 2 + 1] + bg_1;
                *reinterpret_cast<float2*>(
                    out + ((size_t)b * L_SZ + mm) * DM + nc * NCROWS + nlb) = o;
            }
        }
    }
}

// ============================================================
extern "C" void kernel_launch(void* const* d_in, const int* in_sizes, int n_in,
                              void* d_out, int out_size)
{
    const float* x     = (const float*)d_in[0];
    const float* dkp   = (const float*)d_in[1];
    const float* Wexp  = (const float*)d_in[2];
    const float* bexp  = (const float*)d_in[3];
    const float* Wgen  = (const float*)d_in[4];
    const float* bgen  = (const float*)d_in[5];
    const float* Wgate = (const float*)d_in[6];
    const float* bgate = (const float*)d_in[7];
    float* out = (float*)d_out;

    cudaFuncSetAttribute(moe_mma, cudaFuncAttributeMaxDynamicSharedMemorySize, SMEM_TOT);

    const int total_blocks = GATE_NB + A_NB + WE_NB + WG_NB;
    prep_all<<<total_blocks, THREADS>>>(x, dkp, Wgate, bgate, bexp, Wexp, Wgen, bgen);

    dim3 grid(NCHUNK, B_SZ);
    moe_mma<<<grid, THREADS, SMEM_TOT>>>(out);
}

// round 16
// speedup vs baseline: 1.0817x; 1.0242x over previous
#include <cuda_runtime.h>
#include <cuda_fp16.h>
#include <cuda_bf16.h>
#include <cstdint>

#define B_SZ 512
#define L_SZ 128
#define F3   900
#define DM   512
#define DLLM 4096
#define NE   8
#define EPS_RENORM 1e-9f

#define BK      64
#define KTILES  15          // 14 full + 1 partial (only ks=0 live: 896+16 >= 900)
#define KPAD    960
#define NCHUNK  8
#define NCROWS  64          // DM / NCHUNK
#define THREADS 256

// smem stage layout (Swizzle<3,4,3> on 128B rows)
#define A_OFF  0
#define B_OFF  16384
#define STG    32768        // A 16KB + B (64E+64G rows x 128B) 16KB
#define NBUF   3
#define SMEM_TOT (NBUF * STG)   // 98304 -> 2 CTAs/SM

// overlap chunking
#define NCHB    8            // batch chunks
#define CHB     64           // batches per chunk
#define A_CH_NB 3840         // 64*128*120/256 blocks per prep_a chunk

// prep_head block ranges
#define GATE_NB 512
#define WE_NB   1920         // 8*8*120*64 / 256
#define WG_NB   240          // 8*120*64 / 256
#define HEAD_NB (GATE_NB + WE_NB + WG_NB)

// ---------------- device scratch ----------------
__device__ int   g_eidx[B_SZ];
__device__ float g_scale[B_SZ];
__device__ __align__(16) float g_beff[B_SZ * DM];
__device__ __align__(16) float g_bgsum[DM];
// fp16 weights (single image): [e][nc][n 64][k 960]
__device__ __align__(16) __half g_BE[(size_t)NE * NCHUNK * NCROWS * KPAD];
__device__ __align__(16) __half g_BG[(size_t)NCHUNK * NCROWS * KPAD];
// fp16 activations (single image): [b][m 128][k 960]
__device__ __align__(16) __half g_AH[(size_t)B_SZ * L_SZ * KPAD];

// ---------------- helpers ----------------
__device__ __forceinline__ uint32_t smem_u32(const void* p) {
    uint32_t a;
    asm("{ .reg .u64 t; cvta.to.shared.u64 t, %1; cvt.u32.u64 %0, t; }" : "=r"(a) : "l"(p));
    return a;
}
__device__ __forceinline__ uint32_t sw(uint32_t off) {    // Swizzle<3,4,3> (128B rows)
    return off ^ (((off >> 7) & 7u) << 4);
}
__device__ __forceinline__ void ldsm4(uint32_t* r, uint32_t addr) {
    asm volatile("ldmatrix.sync.aligned.m8n8.x4.shared.b16 {%0,%1,%2,%3}, [%4];"
                 : "=r"(r[0]), "=r"(r[1]), "=r"(r[2]), "=r"(r[3]) : "r"(addr));
}
__device__ __forceinline__ void hmma(float* c, const uint32_t* a, uint32_t b0, uint32_t b1) {
    asm volatile(
        "mma.sync.aligned.m16n8k16.row.col.f32.f16.f16.f32 "
        "{%0,%1,%2,%3}, {%4,%5,%6,%7}, {%8,%9}, {%0,%1,%2,%3};"
        : "+f"(c[0]), "+f"(c[1]), "+f"(c[2]), "+f"(c[3])
        : "r"(a[0]), "r"(a[1]), "r"(a[2]), "r"(a[3]), "r"(b0), "r"(b1));
}
__device__ __forceinline__ void cpasync16(uint32_t dst, const void* src) {
    asm volatile("cp.async.cg.shared.global [%0], [%1], 16;" :: "r"(dst), "l"(src));
}
#define CP_COMMIT() asm volatile("cp.async.commit_group;" ::: "memory")
#define CP_WAIT1()  asm volatile("cp.async.wait_group 1;" ::: "memory")

// ============================================================
// prep_head: gate (one block per batch) + weight conversion.
// ============================================================
__global__ __launch_bounds__(THREADS) void prep_head(
    const float* __restrict__ dkp, const float* __restrict__ Wg,
    const float* __restrict__ bg,  const float* __restrict__ bexp,
    const float* __restrict__ We,
    const float* __restrict__ Wgen, const float* __restrict__ bgen)
{
    const int bid = blockIdx.x;
    const int tid = threadIdx.x;

    if (bid < GATE_NB) {
        // ---------------- gate ----------------
        const int b = bid;
        float acc[NE];
#pragma unroll
        for (int e = 0; e < NE; e++) acc[e] = 0.f;
        const float4* dk4 = reinterpret_cast<const float4*>(dkp + (size_t)b * DLLM);
        for (int k4 = tid; k4 < DLLM / 4; k4 += THREADS) {
            float4 xv4 = dk4[k4];
            float xs[4] = {xv4.x, xv4.y, xv4.z, xv4.w};
#pragma unroll
            for (int j = 0; j < 4; j++) {
                const float4* wr = reinterpret_cast<const float4*>(Wg + (size_t)(k4 * 4 + j) * NE);
                float4 w0 = wr[0], w1 = wr[1];
                float xv = xs[j];
                acc[0] += xv * w0.x; acc[1] += xv * w0.y; acc[2] += xv * w0.z; acc[3] += xv * w0.w;
                acc[4] += xv * w1.x; acc[5] += xv * w1.y; acc[6] += xv * w1.z; acc[7] += xv * w1.w;
            }
        }
        __shared__ float red[THREADS][NE];
#pragma unroll
        for (int e = 0; e < NE; e++) red[tid][e] = acc[e];
        __syncthreads();
        for (int s = THREADS / 2; s > 0; s >>= 1) {
            if (tid < s) {
#pragma unroll
                for (int e = 0; e < NE; e++) red[tid][e] += red[tid + s][e];
            }
            __syncthreads();
        }
        __shared__ int se;
        __shared__ float ss;
        if (tid == 0) {
            float logit[NE], p[NE], mx = -1e30f;
#pragma unroll
            for (int e = 0; e < NE; e++) { logit[e] = red[0][e] + bg[e]; mx = fmaxf(mx, logit[e]); }
            float s = 0.f;
#pragma unroll
            for (int e = 0; e < NE; e++) { p[e] = expf(logit[e] - mx); s += p[e]; }
            int best = 0;
#pragma unroll
            for (int e = 1; e < NE; e++) if (p[e] > p[best]) best = e;
            float pb = p[best] / s;
            float scale = pb / (pb + EPS_RENORM);
            se = best; ss = scale;
            g_eidx[b] = best; g_scale[b] = scale;
        }
        __syncthreads();
        int e = se; float sc = ss;
        for (int d = tid; d < DM; d += THREADS)
            g_beff[(size_t)b * DM + d] = sc * bexp[e * DM + d];
        return;
    }

    if (bid < GATE_NB + WE_NB) {
        // ---------------- prep_we ----------------
        int t = (bid - GATE_NB) * THREADS + tid;
        int n  = t & 63;
        int r  = t >> 6;
        int kg = r % 120; r /= 120;
        int nc = r & 7;   int e = r >> 3;
        int k0 = kg * 8;
        union { __half h[8]; uint4 v; } uh;
#pragma unroll
        for (int j = 0; j < 8; j++) {
            int k = k0 + j;
            float v = (k < F3) ? We[(size_t)e * F3 * DM + (size_t)k * DM + nc * NCROWS + n] : 0.f;
            uh.h[j] = __float2half_rn(v);
        }
        size_t base = (size_t)(e * NCHUNK + nc) * (NCROWS * KPAD) + (size_t)n * KPAD + k0;
        *reinterpret_cast<uint4*>(&g_BE[base]) = uh.v;
        return;
    }

    {
        // ---------------- prep_wg + bgsum ----------------
        int t = (bid - GATE_NB - WE_NB) * THREADS + tid;
        if (t < DM) g_bgsum[t] = bgen[t] + bgen[DM + t];
        int n  = t & 63;
        int r  = t >> 6;
        int kg = r % 120;
        int nc = r / 120;
        int k0 = kg * 8;
        union { __half h[8]; uint4 v; } uh;
#pragma unroll
        for (int j = 0; j < 8; j++) {
            int k = k0 + j;
            float v = 0.f;
            if (k < F3) {
                size_t idx = (size_t)k * DM + nc * NCROWS + n;
                v = Wgen[idx] + Wgen[(size_t)F3 * DM + idx];
            }
            uh.h[j] = __float2half_rn(v);
        }
        size_t base = (size_t)nc * (NCROWS * KPAD) + (size_t)n * KPAD + k0;
        *reinterpret_cast<uint4*>(&g_BG[base]) = uh.v;
    }
}

// ============================================================
// prep_a_chunk: x -> fp16 image for batches [b0, b0+64)
// ============================================================
__global__ __launch_bounds__(THREADS) void prep_a_chunk(
    const float* __restrict__ x, int b0)
{
    int t = blockIdx.x * THREADS + threadIdx.x;
    int q = t % 120;
    int m = (t / 120) % L_SZ;
    int b = b0 + t / (120 * L_SZ);
    int k0 = q * 8;
    const float* xr = x + ((size_t)b * L_SZ + m) * F3;
    float4 v0 = make_float4(0.f, 0.f, 0.f, 0.f);
    float4 v1 = make_float4(0.f, 0.f, 0.f, 0.f);
    if (q < 112) {
        v0 = *reinterpret_cast<const float4*>(xr + k0);
        v1 = *reinterpret_cast<const float4*>(xr + k0 + 4);
    } else if (q == 112) {
        v0 = *reinterpret_cast<const float4*>(xr + k0);
    }
    union { __half h[8]; uint4 v; } uh;
    uh.h[0] = __float2half_rn(v0.x); uh.h[1] = __float2half_rn(v0.y);
    uh.h[2] = __float2half_rn(v0.z); uh.h[3] = __float2half_rn(v0.w);
    uh.h[4] = __float2half_rn(v1.x); uh.h[5] = __float2half_rn(v1.y);
    uh.h[6] = __float2half_rn(v1.z); uh.h[7] = __float2half_rn(v1.w);
    size_t o = ((size_t)b * L_SZ + m) * KPAD + k0;
    *reinterpret_cast<uint4*>(&g_AH[o]) = uh.v;
}

// ============================================================
// Main GEMM (R15, bit-identical math): fp16 mma.sync, expert
// 1-term, gen 1-term (shared A). CTA = (nc, b0+by): 128x64 tile.
// BK=64, 15 stages (last partial, q<2 issue), 3-buf depth-2
// pipeline, hoisted cp.async descriptors, 2 CTAs/SM.
// ============================================================
__global__ __launch_bounds__(THREADS, 2) void moe_mma(float* __restrict__ out, int b0)
{
    extern __shared__ char sm[];
    const int b = b0 + blockIdx.y, nc = blockIdx.x;
    const int tid = threadIdx.x, lane = tid & 31, warp = tid >> 5;
    const int wm = warp & 3, wn = warp >> 2;
    const int m0 = wm * 32, n0 = wn * 32;
    const uint32_t sbase = smem_u32(sm);

    const int   e  = g_eidx[b];
    const float sc = g_scale[b];

    const __half* aH = g_AH + (size_t)b * L_SZ * KPAD;
    const __half* beW = g_BE + (size_t)(e * NCHUNK + nc) * (NCROWS * KPAD);
    const __half* bgW = g_BG + (size_t)nc * (NCROWS * KPAD);

    float accE[2][4][4], accG[2][4][4];
#pragma unroll
    for (int i = 0; i < 2; i++)
#pragma unroll
        for (int j = 0; j < 4; j++)
#pragma unroll
            for (int c = 0; c < 4; c++) { accE[i][j][c] = 0.f; accG[i][j][c] = 0.f; }

    const int arow  = (lane & 7) + 8 * ((lane >> 3) & 1);
    const int acol8 = (lane >> 4);
    const int brow  = (lane & 7) + 8 * (lane >> 4);
    const int bcol8 = (lane >> 3) & 1;

    // ---- hoisted cp.async transfer descriptors (loop-invariant) ----
    const int q = tid & 7;
    uint32_t dA[4], oA[4];
    uint32_t dB[4];
    const __half* pB[4];
#pragma unroll
    for (int t = 0; t < 4; t++) {
        int c = tid + t * 256;
        int m = (c >> 3) & 127;
        dA[t] = A_OFF + sw((uint32_t)m * 128 + q * 16);
        oA[t] = (uint32_t)m * KPAD + q * 8;
        int r = (c >> 3) & 127;
        dB[t] = B_OFF + sw((uint32_t)r * 128 + q * 16);
        pB[t] = ((r < NCROWS) ? beW + (size_t)r * KPAD
                              : bgW + (size_t)(r - NCROWS) * KPAD) + q * 8;
    }

    auto issue = [&](int s, int stg) {
        const uint32_t sb = sbase + stg * STG;
        const uint32_t kof = (uint32_t)s * BK;
#pragma unroll
        for (int t = 0; t < 4; t++) cpasync16(sb + dA[t], aH + oA[t] + kof);
#pragma unroll
        for (int t = 0; t < 4; t++) cpasync16(sb + dB[t], pB[t] + kof);
    };

#define KS_BODY(bufA, bufB, KS) do { \
        uint32_t ah[2][4], be2[2][4], bg2[2][4]; \
        const uint32_t acoff = (KS) * 32 + acol8 * 16; \
        const uint32_t bcoff = (KS) * 32 + bcol8 * 16; \
        _Pragma("unroll") \
        for (int mt = 0; mt < 2; mt++) { \
            uint32_t ro = (uint32_t)(m0 + mt * 16 + arow) * 128; \
            ldsm4(ah[mt], (bufA) + sw(ro + acoff)); \
        } \
        _Pragma("unroll") \
        for (int pp = 0; pp < 2; pp++) { \
            uint32_t roE = (uint32_t)(n0 + pp * 16 + brow) * 128; \
            uint32_t roG = (uint32_t)(NCROWS + n0 + pp * 16 + brow) * 128; \
            ldsm4(be2[pp], (bufB) + sw(roE + bcoff)); \
            ldsm4(bg2[pp], (bufB) + sw(roG + bcoff)); \
        } \
        _Pragma("unroll") \
        for (int mt = 0; mt < 2; mt++) \
            _Pragma("unroll") \
            for (int nt = 0; nt < 4; nt++) \
                hmma(accE[mt][nt], ah[mt], be2[nt >> 1][(nt & 1) * 2], be2[nt >> 1][(nt & 1) * 2 + 1]); \
        _Pragma("unroll") \
        for (int mt = 0; mt < 2; mt++) \
            _Pragma("unroll") \
            for (int nt = 0; nt < 4; nt++) \
                hmma(accG[mt][nt], ah[mt], bg2[nt >> 1][(nt & 1) * 2], bg2[nt >> 1][(nt & 1) * 2 + 1]); \
    } while (0)

    issue(0, 0); CP_COMMIT();
    issue(1, 1); CP_COMMIT();

    for (int s = 0; s < KTILES; s++) {
        const int p = s % NBUF;
        CP_WAIT1();
        __syncthreads();

        const uint32_t bufA = sbase + p * STG;
        const uint32_t bufB = bufA + B_OFF;

        if (s < KTILES - 1) {
            KS_BODY(bufA, bufB, 0);
            if (s + 2 < KTILES) {
                if (s + 2 == KTILES - 1) {
                    if (q < 2) issue(s + 2, (s + 2) % NBUF);
                } else {
                    issue(s + 2, (s + 2) % NBUF);
                }
            }
            CP_COMMIT();
            KS_BODY(bufA, bufB, 1);
            KS_BODY(bufA, bufB, 2);
            KS_BODY(bufA, bufB, 3);
        } else {
            CP_COMMIT();              // keep group count in lockstep
            KS_BODY(bufA, bufB, 0);   // k 896..912 covers F3=900
        }
    }
#undef KS_BODY

    // ---- register epilogue: all warps store their paired tiles ----
    const float* beff = g_beff + (size_t)b * DM + nc * NCROWS;
    const float* bgs  = g_bgsum + nc * NCROWS;
#pragma unroll
    for (int mt = 0; mt < 2; mt++) {
        int mb = m0 + mt * 16 + (lane >> 2);
#pragma unroll
        for (int nt = 0; nt < 4; nt++) {
            int nlb = n0 + nt * 8 + 2 * (lane & 3);
            float be_0 = __ldg(&beff[nlb]),  be_1 = __ldg(&beff[nlb + 1]);
            float bg_0 = __ldg(&bgs[nlb]),   bg_1 = __ldg(&bgs[nlb + 1]);
#pragma unroll
            for (int h = 0; h < 2; h++) {
                int mm = mb + 8 * h;
                float ev0 = sc * accE[mt][nt][h * 2 + 0] + be_0;
                float ev1 = sc * accE[mt][nt][h * 2 + 1] + be_1;
                float2 o;
                o.x = __bfloat162float(__float2bfloat16(ev0)) + accG[mt][nt][h * 2 + 0] + bg_0;
                o.y = __bfloat162float(__float2bfloat16(ev1)) + accG[mt][nt][h * 2 + 1] + bg_1;
                *reinterpret_cast<float2*>(
                    out + ((size_t)b * L_SZ + mm) * DM + nc * NCROWS + nlb) = o;
            }
        }
    }
}

// ============================================================
// Launch: forked-stream software pipeline.
//  sP : prep_head ; prep_a chunk 0..7 (event after each)
//  sM0/sM1 : moe chunk c waits evA[c] (head ordered before A0 on sP)
//  legacy stream: fork root + join all (graph-capture fork/join)
// ============================================================
extern "C" void kernel_launch(void* const* d_in, const int* in_sizes, int n_in,
                              void* d_out, int out_size)
{
    const float* x     = (const float*)d_in[0];
    const float* dkp   = (const float*)d_in[1];
    const float* Wexp  = (const float*)d_in[2];
    const float* bexp  = (const float*)d_in[3];
    const float* Wgen  = (const float*)d_in[4];
    const float* bgen  = (const float*)d_in[5];
    const float* Wgate = (const float*)d_in[6];
    const float* bgate = (const float*)d_in[7];
    float* out = (float*)d_out;

    static cudaStream_t sP = nullptr, sM0 = nullptr, sM1 = nullptr;
    static cudaEvent_t evRoot, evA[NCHB], evJ0, evJ1;
    if (sP == nullptr) {
        cudaStreamCreateWithFlags(&sP,  cudaStreamNonBlocking);
        cudaStreamCreateWithFlags(&sM0, cudaStreamNonBlocking);
        cudaStreamCreateWithFlags(&sM1, cudaStreamNonBlocking);
        cudaEventCreateWithFlags(&evRoot, cudaEventDisableTiming);
        for (int c = 0; c < NCHB; c++)
            cudaEventCreateWithFlags(&evA[c], cudaEventDisableTiming);
        cudaEventCreateWithFlags(&evJ0, cudaEventDisableTiming);
        cudaEventCreateWithFlags(&evJ1, cudaEventDisableTiming);
        cudaFuncSetAttribute(moe_mma, cudaFuncAttributeMaxDynamicSharedMemorySize, SMEM_TOT);
    }

    // fork from the (captured) legacy stream
    cudaEventRecord(evRoot, 0);
    cudaStreamWaitEvent(sP,  evRoot, 0);
    cudaStreamWaitEvent(sM0, evRoot, 0);
    cudaStreamWaitEvent(sM1, evRoot, 0);

    // producer stream: head then A chunks
    prep_head<<<HEAD_NB, THREADS, 0, sP>>>(dkp, Wgate, bgate, bexp, Wexp, Wgen, bgen);
    for (int c = 0; c < NCHB; c++) {
        prep_a_chunk<<<A_CH_NB, THREADS, 0, sP>>>(x, c * CHB);
        cudaEventRecord(evA[c], sP);
    }

    // consumer streams: moe chunks, alternating for backfill
    for (int c = 0; c < NCHB; c++) {
        cudaStream_t s = (c & 1) ? sM1 : sM0;
        cudaStreamWaitEvent(s, evA[c], 0);
        dim3 grid(NCHUNK, CHB);
        moe_mma<<<grid, THREADS, SMEM_TOT, s>>>(out, c * CHB);
    }

    // join everything back into the legacy (capture) stream
    cudaEventRecord(evJ0, sM0);
    cudaEventRecord(evJ1, sM1);
    cudaStreamWaitEvent(0, evA[NCHB - 1], 0);   // joins sP
    cudaStreamWaitEvent(0, evJ0, 0);
    cudaStreamWaitEvent(0, evJ1, 0);
}